// round 1
// baseline (speedup 1.0000x reference)
#include <cuda_runtime.h>

#define N 8192
#define ROWS_PER_BLK 64
#define COLS_PER_BLK 2048
#define CB 4     /* column tiles */
#define RB 128   /* row tiles */
#define THREADS 256

// Scratch (no device allocation allowed -> __device__ globals)
__device__ float g_rowpart[CB * N];   // [cb][row]  : partial row sums per column tile
__device__ float g_colpart[RB * N];   // [rb][col]  : partial col sums per row tile (4 MiB)
__device__ float g_imb[N];            // |rowsum - colsum| per index

// ---------------------------------------------------------------------------
// Pass 1: one block per 64x2048 tile. Single read of the 256 MiB matrix.
// Each float4 load feeds BOTH the row-sum path (warp shuffle reduce) and the
// col-sum path (per-thread register accumulators over the 64 rows).
// ---------------------------------------------------------------------------
__global__ void __launch_bounds__(THREADS)
tile_kernel(const float* __restrict__ flow)
{
    const int cb   = blockIdx.x;          // 0..3
    const int rb   = blockIdx.y;          // 0..127
    const int t    = threadIdx.x;         // 0..255
    const int warp = t >> 5;
    const int lane = t & 31;
    const int row0 = rb * ROWS_PER_BLK;
    const int col0 = cb * COLS_PER_BLK;

    __shared__ float s_row[ROWS_PER_BLK][8];   // per-warp row partials (2 KB)

    // Thread t owns float4 columns {t, t+256} within the tile -> 8 scalar cols
    float4 c0 = make_float4(0.f, 0.f, 0.f, 0.f);
    float4 c1 = make_float4(0.f, 0.f, 0.f, 0.f);

    const float4* base = reinterpret_cast<const float4*>(flow)
                         + (size_t)row0 * (N / 4) + (col0 / 4);

    #pragma unroll 4
    for (int r = 0; r < ROWS_PER_BLK; ++r) {
        const float4* rp = base + (size_t)r * (N / 4);
        float4 a = __ldg(rp + t);
        float4 b = __ldg(rp + t + THREADS);

        // column accumulation (register-resident)
        c0.x += a.x; c0.y += a.y; c0.z += a.z; c0.w += a.w;
        c1.x += b.x; c1.y += b.y; c1.z += b.z; c1.w += b.w;

        // row accumulation: per-thread partial -> warp reduce -> smem
        float s = (a.x + a.y) + (a.z + a.w) + (b.x + b.y) + (b.z + b.w);
        s += __shfl_xor_sync(0xffffffffu, s, 16);
        s += __shfl_xor_sync(0xffffffffu, s, 8);
        s += __shfl_xor_sync(0xffffffffu, s, 4);
        s += __shfl_xor_sync(0xffffffffu, s, 2);
        s += __shfl_xor_sync(0xffffffffu, s, 1);
        if (lane == 0) s_row[r][warp] = s;
    }

    // Column partials: unique writer per (rb, col) -> plain stores, no atomics
    float4* cp = reinterpret_cast<float4*>(g_colpart + (size_t)rb * N + col0);
    cp[t]           = c0;
    cp[t + THREADS] = c1;

    __syncthreads();

    // Row partials: unique writer per (cb, row)
    if (t < ROWS_PER_BLK) {
        float s = 0.f;
        #pragma unroll
        for (int w = 0; w < 8; ++w) s += s_row[t][w];
        g_rowpart[cb * N + row0 + t] = s;
    }
}

// ---------------------------------------------------------------------------
// Pass 2: imb[i] = sum_cb rowpart - sum_rb colpart ; store |imb|.
// 4 MiB of L2-resident scratch read; deterministic fixed-order sums.
// ---------------------------------------------------------------------------
__global__ void __launch_bounds__(256)
combine_kernel(void)
{
    const int i = blockIdx.x * 256 + threadIdx.x;   // 0..8191

    float rs = 0.f;
    #pragma unroll
    for (int cb = 0; cb < CB; ++cb) rs += g_rowpart[cb * N + i];

    float cs = 0.f;
    #pragma unroll 8
    for (int rb = 0; rb < RB; ++rb) cs += g_colpart[rb * N + i];

    g_imb[i] = fabsf(rs - cs);
}

// ---------------------------------------------------------------------------
// Pass 3: deterministic reduction of 8192 values -> scalar out.
// ---------------------------------------------------------------------------
__global__ void __launch_bounds__(1024)
final_kernel(float* __restrict__ out)
{
    const int t    = threadIdx.x;
    const int warp = t >> 5;
    const int lane = t & 31;

    float s = 0.f;
    #pragma unroll
    for (int k = 0; k < N / 1024; ++k) s += g_imb[t + k * 1024];

    s += __shfl_xor_sync(0xffffffffu, s, 16);
    s += __shfl_xor_sync(0xffffffffu, s, 8);
    s += __shfl_xor_sync(0xffffffffu, s, 4);
    s += __shfl_xor_sync(0xffffffffu, s, 2);
    s += __shfl_xor_sync(0xffffffffu, s, 1);

    __shared__ float sw[32];
    if (lane == 0) sw[warp] = s;
    __syncthreads();

    if (warp == 0) {
        float v = sw[lane];
        v += __shfl_xor_sync(0xffffffffu, v, 16);
        v += __shfl_xor_sync(0xffffffffu, v, 8);
        v += __shfl_xor_sync(0xffffffffu, v, 4);
        v += __shfl_xor_sync(0xffffffffu, v, 2);
        v += __shfl_xor_sync(0xffffffffu, v, 1);
        if (lane == 0) out[0] = v;
    }
}

extern "C" void kernel_launch(void* const* d_in, const int* in_sizes, int n_in,
                              void* d_out, int out_size)
{
    (void)in_sizes; (void)n_in; (void)out_size;
    const float* flow = (const float*)d_in[0];
    float* out = (float*)d_out;

    tile_kernel<<<dim3(CB, RB), THREADS>>>(flow);
    combine_kernel<<<N / 256, 256>>>();
    final_kernel<<<1, 1024>>>(out);
}

// round 2
// speedup vs baseline: 1.2429x; 1.2429x over previous
#include <cuda_runtime.h>

#define N 8192
#define ROWS_PER_BLK 32
#define COLS_PER_BLK 2048
#define CB 4      /* column tiles: 8192/2048 */
#define RB 256    /* row tiles:    8192/32   */
#define THREADS 256
#define RB_CHUNKS 8           /* combine stage-1 chunks */
#define RB_PER_CHUNK (RB / RB_CHUNKS)   /* 32 */

// Scratch (no device allocation allowed -> __device__ globals)
__device__ float g_rowpart[CB * N];        // [cb][row]   partial row sums
__device__ float g_colpart[RB * N];        // [rb][col]   partial col sums (8 MiB)
__device__ float g_cpart2[RB_CHUNKS * N];  // stage-1 folded col partials (256 KB)

// ---------------------------------------------------------------------------
// Pass 1: one block per 32x2048 tile (1024 blocks -> ~86% occupancy).
// Single streaming read (__ldcs, evict-first) of the 256 MiB matrix.
// Each float4 feeds BOTH the row path (warp shuffle reduce) and the
// col path (register accumulators over the 32 rows).
// ---------------------------------------------------------------------------
__global__ void __launch_bounds__(THREADS)
tile_kernel(const float* __restrict__ flow)
{
    const int cb   = blockIdx.x;          // 0..3
    const int rb   = blockIdx.y;          // 0..255
    const int t    = threadIdx.x;         // 0..255
    const int warp = t >> 5;
    const int lane = t & 31;
    const int row0 = rb * ROWS_PER_BLK;
    const int col0 = cb * COLS_PER_BLK;

    __shared__ float s_row[ROWS_PER_BLK][8];   // per-warp row partials (1 KB)

    // Thread t owns float4 columns {t, t+256} within the tile -> 8 scalar cols
    float4 c0 = make_float4(0.f, 0.f, 0.f, 0.f);
    float4 c1 = make_float4(0.f, 0.f, 0.f, 0.f);

    const float4* base = reinterpret_cast<const float4*>(flow)
                         + (size_t)row0 * (N / 4) + (col0 / 4);

    #pragma unroll 4
    for (int r = 0; r < ROWS_PER_BLK; ++r) {
        const float4* rp = base + (size_t)r * (N / 4);
        float4 a = __ldcs(rp + t);            // streaming: don't pollute L2
        float4 b = __ldcs(rp + t + THREADS);

        c0.x += a.x; c0.y += a.y; c0.z += a.z; c0.w += a.w;
        c1.x += b.x; c1.y += b.y; c1.z += b.z; c1.w += b.w;

        float s = (a.x + a.y) + (a.z + a.w) + (b.x + b.y) + (b.z + b.w);
        s += __shfl_xor_sync(0xffffffffu, s, 16);
        s += __shfl_xor_sync(0xffffffffu, s, 8);
        s += __shfl_xor_sync(0xffffffffu, s, 4);
        s += __shfl_xor_sync(0xffffffffu, s, 2);
        s += __shfl_xor_sync(0xffffffffu, s, 1);
        if (lane == 0) s_row[r][warp] = s;
    }

    // Column partials: unique writer per (rb, col) -> plain stores, no atomics
    float4* cp = reinterpret_cast<float4*>(g_colpart + (size_t)rb * N + col0);
    cp[t]           = c0;
    cp[t + THREADS] = c1;

    __syncthreads();

    // Row partials: unique writer per (cb, row)
    if (t < ROWS_PER_BLK) {
        float s = 0.f;
        #pragma unroll
        for (int w = 0; w < 8; ++w) s += s_row[t][w];
        g_rowpart[cb * N + row0 + t] = s;
    }
}

// ---------------------------------------------------------------------------
// Pass 2 (stage-1 fold): 256 blocks. Block (bx, by) folds 32 rb-partials for
// 256 columns. 32 coalesced loads per thread; mostly L2-resident.
// ---------------------------------------------------------------------------
__global__ void __launch_bounds__(256)
combine_kernel(void)
{
    const int i   = blockIdx.x * 256 + threadIdx.x;   // column 0..8191
    const int rb0 = blockIdx.y * RB_PER_CHUNK;

    float cs = 0.f;
    #pragma unroll 8
    for (int j = 0; j < RB_PER_CHUNK; ++j)
        cs += g_colpart[(size_t)(rb0 + j) * N + i];

    g_cpart2[blockIdx.y * N + i] = cs;
}

// ---------------------------------------------------------------------------
// Pass 3: single block. Per column: fold 4 row partials + 8 col partials,
// take |.|, then deterministic tree reduction to the scalar.
// ---------------------------------------------------------------------------
__global__ void __launch_bounds__(1024)
final_kernel(float* __restrict__ out)
{
    const int t    = threadIdx.x;
    const int warp = t >> 5;
    const int lane = t & 31;

    float s = 0.f;
    #pragma unroll
    for (int k = 0; k < N / 1024; ++k) {
        const int i = t + k * 1024;
        float rs = 0.f;
        #pragma unroll
        for (int cb = 0; cb < CB; ++cb) rs += g_rowpart[cb * N + i];
        float cs = 0.f;
        #pragma unroll
        for (int p = 0; p < RB_CHUNKS; ++p) cs += g_cpart2[p * N + i];
        s += fabsf(rs - cs);
    }

    s += __shfl_xor_sync(0xffffffffu, s, 16);
    s += __shfl_xor_sync(0xffffffffu, s, 8);
    s += __shfl_xor_sync(0xffffffffu, s, 4);
    s += __shfl_xor_sync(0xffffffffu, s, 2);
    s += __shfl_xor_sync(0xffffffffu, s, 1);

    __shared__ float sw[32];
    if (lane == 0) sw[warp] = s;
    __syncthreads();

    if (warp == 0) {
        float v = sw[lane];
        v += __shfl_xor_sync(0xffffffffu, v, 16);
        v += __shfl_xor_sync(0xffffffffu, v, 8);
        v += __shfl_xor_sync(0xffffffffu, v, 4);
        v += __shfl_xor_sync(0xffffffffu, v, 2);
        v += __shfl_xor_sync(0xffffffffu, v, 1);
        if (lane == 0) out[0] = v;
    }
}

extern "C" void kernel_launch(void* const* d_in, const int* in_sizes, int n_in,
                              void* d_out, int out_size)
{
    (void)in_sizes; (void)n_in; (void)out_size;
    const float* flow = (const float*)d_in[0];
    float* out = (float*)d_out;

    tile_kernel<<<dim3(CB, RB), THREADS>>>(flow);
    combine_kernel<<<dim3(N / 256, RB_CHUNKS), 256>>>();
    final_kernel<<<1, 1024>>>(out);
}